// round 6
// baseline (speedup 1.0000x reference)
#include <cuda_runtime.h>

// Blocks_86096914416144 — SNN block scan, R6:
// R5 (57.8us) + ONE change: carry spike flags / maskf / decay-count out of the
// store loop instead of recomputing from z at the next iteration's head
// (-~35 instrs/iter of ~195). No smem table, no cache hints (R3 suspects).
// Rationale: runtime ~= instrs/iter / issue-rate (R5 arithmetic check matched
// measured duration); memory is sub-saturated because the loop issues slowly.
// FP operation ordering identical to R2/R5 (rel_err 0.0).

#define T_LEN   1024
#define TB      8
#define NBLK    (T_LEN / TB)      // 128
#define BATCH   32
#define NOUT    1024
#define BN      (BATCH * NOUT)    // 32768
#define CTA     128

__global__ __launch_bounds__(CTA)
void blocks_snn_kernel(const float* __restrict__ x,
                       const float* __restrict__ beta_raw,
                       const float* __restrict__ p_raw,
                       const float* __restrict__ b_raw,
                       float* __restrict__ out)
{
    const int tid = blockIdx.x * CTA + threadIdx.x;   // 0..32767
    const int n   = tid & (NOUT - 1);

    const float beta  = fminf(fmaxf(beta_raw[n], 0.001f), 0.999f);
    const float p     = fminf(fmaxf(fabsf(p_raw[n]), 0.0f), 0.999f);
    const float bb    = fminf(fmaxf(fabsf(b_raw[n]), 0.001f), 1.0f);
    const float inv_p = 1.0f / p;

    float bpow[TB];
    bpow[0] = 1.0f;
    #pragma unroll
    for (int k = 1; k < TB; k++) bpow[k] = powf(beta, (float)k);

    float ppow[TB + 1];
    ppow[0] = 1.0f;
    #pragma unroll
    for (int k = 1; k <= TB; k++) ppow[k] = powf(p, (float)k);

    // carry state
    float z[TB];                       // z_new from previous block
    float sp[TB];                      // (z == 1) spike flags from prev block
    #pragma unroll
    for (int t = 0; t < TB; t++) { z[t] = 0.0f; sp[t] = 0.0f; }
    float maskf = 0.0f;                // any spike in previous block
    int   ds    = 0;                   // count(z > 1) from previous block
    float a     = 0.0f;
    float vmem  = 0.0f;

    const float* xp = x + tid;
    float*       op = out + tid;

    // 4-slot register ring, prefetch 3 blocks ahead
    float buf[4][TB];
    #pragma unroll
    for (int pb = 0; pb < 3; pb++) {
        const float* xb = xp + (size_t)pb * TB * BN;
        #pragma unroll
        for (int t = 0; t < TB; t++) buf[pb][t] = xb[t * BN];
    }

    #pragma unroll 1
    for (int g = 0; g < NBLK / 4; g++) {
        #pragma unroll
        for (int u = 0; u < 4; u++) {
            const int blk = 4 * g + u;

            // prefetch blk+3 into the slot freed last iteration
            if (blk + 3 < NBLK) {
                const float* xb = xp + (size_t)(blk + 3) * TB * BN;
                #pragma unroll
                for (int t = 0; t < TB; t++)
                    buf[(u + 3) & 3][t] = xb[t * BN];
            }
            const float* xc = buf[u & 3];

            // ---- adaptation update (sp, maskf, ds carried from last iter) ----
            // a_at_spike = sum_t p^(t+1)*a*sg[t] + 1/p  (same order as R2)
            float a_at = 0.0f;
            #pragma unroll
            for (int t = 0; t < TB; t++)
                if (sp[t] != 0.0f) a_at += ppow[t + 1] * a;
            a_at += inv_p;

            // p^ds via register select chain (exact powf values)
            float pds = ppow[0];
            #pragma unroll
            for (int k = 1; k <= TB; k++)
                if (ds == k) pds = ppow[k];

            const float new_a = a_at * pds;
            a = (maskf != 0.0f) ? new_a : (ppow[TB] * a);

            // ---- refractory masking + membrane carry-in ----
            const float v_init = vmem * (1.0f - maskf);
            float cur[TB];
            #pragma unroll
            for (int t = 0; t < TB; t++)
                cur[t] = (z[t] < maskf) ? 0.0f : xc[t];
            cur[0] = cur[0] + beta * v_init;

            // ---- causal decayed sum + threshold (ordering preserved) ----
            float f[TB];
            float mlast = 0.0f;
            #pragma unroll
            for (int t = 0; t < TB; t++) {
                float m = 0.0f;
                #pragma unroll
                for (int s = 0; s <= t; s++)
                    m += bpow[t - s] * cur[s];
                const float vth = 1.0f + bb * (ppow[t + 1] * a);
                f[t] = ((m - vth) > 0.0f) ? 1.0f : 0.0f;
                if (t == TB - 1) mlast = m;
            }

            // ---- z = double cumsum; emit spikes; fold next-iter carries ----
            float* ob = op + (size_t)blk * TB * BN;
            float c = 0.0f, zr = 0.0f;
            float nmask = 0.0f;
            int   nds   = 0;
            #pragma unroll
            for (int t = 0; t < TB; t++) {
                c  += f[t];
                zr += c;
                z[t] = zr;
                const float spike = (zr == 1.0f) ? 1.0f : 0.0f;
                sp[t] = spike;
                nmask = fmaxf(nmask, spike);
                if (zr > 1.0f) nds++;
                ob[t * BN] = spike;
            }
            maskf = nmask;
            ds    = nds;
            vmem  = mlast;
        }
    }
}

extern "C" void kernel_launch(void* const* d_in, const int* in_sizes, int n_in,
                              void* d_out, int out_size)
{
    const float* x        = (const float*)d_in[0];
    const float* beta_raw = (const float*)d_in[1];
    const float* p_raw    = (const float*)d_in[2];
    const float* b_raw    = (const float*)d_in[3];
    float* out = (float*)d_out;

    blocks_snn_kernel<<<BN / CTA, CTA>>>(x, beta_raw, p_raw, b_raw, out);
}

// round 7
// speedup vs baseline: 1.0224x; 1.0224x over previous
#include <cuda_runtime.h>

// Blocks_86096914416144 — SNN block scan, R7: first-spike-index carry.
// Exact identity: z[t] = sum_{s<=t}(t-s+1) f[s] with f in {0,1} implies
//   z[t0]=1 (t0 = first spike), z[t]=0 before, z[t]>=2 after.
// So spikes out = one-hot(t0), maskf = (t0 exists), sg one-hot at t0,
// decay_steps = TB-1-t0, refractory mask = (t < t0_prev).
// Entire double-cumsum + z/sp carry removed; carry = {t0, a, vmem}.
// Membrane sums / vth / a-update keep R5's exact FP ordering.

#define T_LEN   1024
#define TB      8
#define NBLK    (T_LEN / TB)      // 128
#define BATCH   32
#define NOUT    1024
#define BN      (BATCH * NOUT)    // 32768
#define CTA     128

__global__ __launch_bounds__(CTA)
void blocks_snn_kernel(const float* __restrict__ x,
                       const float* __restrict__ beta_raw,
                       const float* __restrict__ p_raw,
                       const float* __restrict__ b_raw,
                       float* __restrict__ out)
{
    const int tid = blockIdx.x * CTA + threadIdx.x;   // 0..32767
    const int n   = tid & (NOUT - 1);

    const float beta  = fminf(fmaxf(beta_raw[n], 0.001f), 0.999f);
    const float p     = fminf(fmaxf(fabsf(p_raw[n]), 0.0f), 0.999f);
    const float bb    = fminf(fmaxf(fabsf(b_raw[n]), 0.001f), 1.0f);
    const float inv_p = 1.0f / p;

    float bpow[TB];
    bpow[0] = 1.0f;
    #pragma unroll
    for (int k = 1; k < TB; k++) bpow[k] = powf(beta, (float)k);

    float ppow[TB + 1];
    ppow[0] = 1.0f;
    #pragma unroll
    for (int k = 1; k <= TB; k++) ppow[k] = powf(p, (float)k);

    // carry: first-spike index of previous block (TB = none), a, vmem
    int   t0p  = TB;
    float a    = 0.0f;
    float vmem = 0.0f;

    const float* xp = x + tid;
    float*       op = out + tid;

    // 4-slot register ring, prefetch 3 blocks ahead
    float buf[4][TB];
    #pragma unroll
    for (int pb = 0; pb < 3; pb++) {
        const float* xb = xp + (size_t)pb * TB * BN;
        #pragma unroll
        for (int t = 0; t < TB; t++) buf[pb][t] = xb[t * BN];
    }

    #pragma unroll 1
    for (int g = 0; g < NBLK / 4; g++) {
        #pragma unroll
        for (int u = 0; u < 4; u++) {
            const int blk = 4 * g + u;

            if (blk + 3 < NBLK) {
                const float* xb = xp + (size_t)(blk + 3) * TB * BN;
                #pragma unroll
                for (int t = 0; t < TB; t++)
                    buf[(u + 3) & 3][t] = xb[t * BN];
            }
            const float* xc = buf[u & 3];

            const bool  spiked = (t0p < TB);
            const float maskf  = spiked ? 1.0f : 0.0f;

            // ---- adaptation update ----
            // sg one-hot at t0p: a_at = p^(t0p+1)*a + inv_p ; pds = p^(TB-1-t0p)
            float pt  = ppow[1];
            float pds = ppow[TB - 1];
            #pragma unroll
            for (int k = 1; k < TB; k++)
                if (t0p == k) { pt = ppow[k + 1]; pds = ppow[TB - 1 - k]; }
            // reference order: (0 + p^(t0+1)*a) + inv_p, then * p^ds
            const float a_at  = __fadd_rn(__fmul_rn(pt, a), inv_p);
            const float new_a = __fmul_rn(a_at, pds);
            a = spiked ? new_a : (ppow[TB] * a);

            // ---- refractory masking + membrane carry-in ----
            const float v_init = vmem * (1.0f - maskf);
            const int   mstart = spiked ? t0p : 0;
            float cur[TB];
            #pragma unroll
            for (int t = 0; t < TB; t++)
                cur[t] = (t < mstart) ? 0.0f : xc[t];
            cur[0] = cur[0] + beta * v_init;

            // ---- causal decayed sums + threshold; first crossing ----
            int cand[TB];
            float mlast = 0.0f;
            #pragma unroll
            for (int t = 0; t < TB; t++) {
                float m = 0.0f;
                #pragma unroll
                for (int s = 0; s <= t; s++)
                    m += bpow[t - s] * cur[s];      // exact R5 ordering
                const float vth = 1.0f + bb * (ppow[t + 1] * a);
                cand[t] = ((m - vth) > 0.0f) ? t : TB;
                if (t == TB - 1) mlast = m;
            }
            // min-tree: first spike index (TB if none)
            const int m01 = min(cand[0], cand[1]);
            const int m23 = min(cand[2], cand[3]);
            const int m45 = min(cand[4], cand[5]);
            const int m67 = min(cand[6], cand[7]);
            const int t0  = min(min(m01, m23), min(m45, m67));

            // ---- one-hot spike output ----
            float* ob = op + (size_t)blk * TB * BN;
            #pragma unroll
            for (int t = 0; t < TB; t++)
                ob[t * BN] = (t == t0) ? 1.0f : 0.0f;

            t0p  = t0;
            vmem = mlast;
        }
    }
}

extern "C" void kernel_launch(void* const* d_in, const int* in_sizes, int n_in,
                              void* d_out, int out_size)
{
    const float* x        = (const float*)d_in[0];
    const float* beta_raw = (const float*)d_in[1];
    const float* p_raw    = (const float*)d_in[2];
    const float* b_raw    = (const float*)d_in[3];
    float* out = (float*)d_out;

    blocks_snn_kernel<<<BN / CTA, CTA>>>(x, beta_raw, p_raw, b_raw, out);
}